// round 6
// baseline (speedup 1.0000x reference)
#include <cuda_runtime.h>
#include <math.h>

#define BB 128
#define TT 512
#define WW 64
#define DD 128
#define CC 256
#define KS 12
#define TP 500

// ---------------- device scratch (no runtime allocation allowed) ----------------
__device__ float g_z[(size_t)BB * TT * DD];        // 33.5 MB  (B,T,D) normalized z
__device__ float g_xp[(size_t)BB * TT * 3 * CC];   // 201 MB   (B,T,768) x_proj (= z@Wi + bi)
__device__ float g_c[(size_t)BB * TT * CC];        // 67 MB    (B,T,C) GRU hidden states
__device__ float g_whT[3 * CC * CC];               // Wh transposed: [col(0..767)][k(0..255)]
__device__ double g_loss;
__device__ int    g_cnt;

// ---------------- init accumulators ----------------
__global__ void k_init() { g_loss = 0.0; g_cnt = 0; }

// ---------------- transpose Wh once per launch ----------------
__global__ void k_wht(const float* __restrict__ Wh) {
    int i = blockIdx.x * 256 + threadIdx.x;       // i = col*256 + kk
    if (i < 3 * CC * CC) {
        int kk = i & 255;
        int col = i >> 8;
        g_whT[i] = Wh[(size_t)kk * 768 + col];
    }
}

// ---------------- z = l2norm(rr @ We + be) ----------------
// grid (T/64, B), block 128 (one thread per d)
__global__ __launch_bounds__(128) void k_z(const float* __restrict__ rr,
                                           const float* __restrict__ We,
                                           const float* __restrict__ be) {
    __shared__ float Wes[64 * 128];
    __shared__ float rs[64];
    __shared__ float red[4];
    int b = blockIdx.y;
    int t0 = blockIdx.x << 6;
    int tid = threadIdx.x;
    for (int i = tid; i < 64 * 128; i += 128) Wes[i] = We[i];
    float bias = be[tid];
    __syncthreads();
    for (int tt = 0; tt < 64; tt++) {
        int t = t0 + tt;
        if (tid < 64) rs[tid] = rr[((size_t)b * TT + t) * WW + tid];
        __syncthreads();
        float acc = bias;
#pragma unroll
        for (int w = 0; w < 64; w++) acc += rs[w] * Wes[w * 128 + tid];
        float ss = acc * acc;
#pragma unroll
        for (int o = 16; o; o >>= 1) ss += __shfl_xor_sync(0xffffffffu, ss, o);
        if ((tid & 31) == 0) red[tid >> 5] = ss;
        __syncthreads();
        float tot = red[0] + red[1] + red[2] + red[3];
        float scale = 1.0f / fmaxf(sqrtf(tot), 1e-12f);
        g_z[((size_t)b * TT + t) * DD + tid] = acc * scale;
        __syncthreads();
    }
}

// ---------------- x_proj = z @ Wi + bi  (M=65536, N=768, K=128) ----------------
// grid (6, 512), block 256, 128x128 tile, 8x8 per thread
__global__ __launch_bounds__(256) void k_xproj(const float* __restrict__ Wi,
                                               const float* __restrict__ bi) {
    __shared__ float As[32 * 132];  // [kk][r]
    __shared__ float Bs[32 * 132];  // [kk][n]
    int tid = threadIdx.x;
    int tx = tid & 15, ty = tid >> 4;
    int m0 = blockIdx.y << 7, n0 = blockIdx.x << 7;
    float acc[8][8] = {};
    for (int kc = 0; kc < DD; kc += 32) {
        for (int i = tid; i < 4096; i += 256) {
            int r = i >> 5, kk = i & 31;
            As[kk * 132 + r] = g_z[(size_t)(m0 + r) * DD + kc + kk];
        }
        for (int i = tid; i < 4096; i += 256) {
            int kk = i >> 7, n = i & 127;
            Bs[kk * 132 + n] = Wi[(size_t)(kc + kk) * 768 + n0 + n];
        }
        __syncthreads();
#pragma unroll
        for (int kk = 0; kk < 32; kk++) {
            float4 a1 = *(const float4*)&As[kk * 132 + ty * 4];
            float4 a2 = *(const float4*)&As[kk * 132 + 64 + ty * 4];
            float4 b1 = *(const float4*)&Bs[kk * 132 + tx * 4];
            float4 b2 = *(const float4*)&Bs[kk * 132 + 64 + tx * 4];
            float av[8] = {a1.x, a1.y, a1.z, a1.w, a2.x, a2.y, a2.z, a2.w};
            float bv[8] = {b1.x, b1.y, b1.z, b1.w, b2.x, b2.y, b2.z, b2.w};
#pragma unroll
            for (int i = 0; i < 8; i++)
#pragma unroll
                for (int j = 0; j < 8; j++) acc[i][j] += av[i] * bv[j];
        }
        __syncthreads();
    }
#pragma unroll
    for (int i = 0; i < 8; i++) {
        int r = m0 + ((i < 4) ? ty * 4 + i : 64 + ty * 4 + i - 4);
#pragma unroll
        for (int j = 0; j < 8; j++) {
            int c = n0 + ((j < 4) ? tx * 4 + j : 64 + tx * 4 + j - 4);
            g_xp[(size_t)r * 768 + c] = acc[i][j] + bi[c];
        }
    }
}

// ---------------- one GRU timestep ----------------
// grid (8 c-chunks, 16 row-chunks), block 128
#define GRU_SMEM ((3 * 32 * 260 + 8 * 256) * 4)
__global__ __launch_bounds__(128) void k_gru(const float* __restrict__ bh, int t) {
    extern __shared__ float sm[];
    float* ws = sm;                  // [g*32+c][260] (pad for bank spread)
    float* hs = sm + 3 * 32 * 260;   // [8][256]
    int tid = threadIdx.x;
    int cb0 = blockIdx.x << 5;
    int rb0 = blockIdx.y << 3;

    // stage Wh slice: fully coalesced float4 from pre-transposed g_whT
    for (int i = tid * 4; i < 3 * 32 * 256; i += 128 * 4) {
        int cc = i >> 8;             // 0..95 == g*32+c
        int kk = i & 255;
        int g = cc >> 5, c = cc & 31;
        float4 v = *(const float4*)&g_whT[((size_t)(g * 256 + cb0 + c)) * 256 + kk];
        *(float4*)&ws[(size_t)cc * 260 + kk] = v;
    }
    // stage h_{t-1} rows (full C)
    for (int i = tid * 4; i < 8 * 256; i += 128 * 4) {
        int r = i >> 8, kk = i & 255;
        float4 v;
        if (t == 0) v = make_float4(0.f, 0.f, 0.f, 0.f);
        else v = *(const float4*)&g_c[((size_t)(rb0 + r) * TT + (t - 1)) * CC + kk];
        *(float4*)&hs[r * 256 + kk] = v;
    }
    __syncthreads();

    int c = tid & 31;
    int rp = tid >> 5;  // 0..3, each handles 2 rows
    const float4* wr4 = (const float4*)&ws[(0 + c) * 260];
    const float4* wz4 = (const float4*)&ws[(32 + c) * 260];
    const float4* wn4 = (const float4*)&ws[(64 + c) * 260];
    const float4* h0 = (const float4*)&hs[(rp * 2) * 256];
    const float4* h1 = (const float4*)&hs[(rp * 2 + 1) * 256];
    float a00 = 0, a01 = 0, a02 = 0, a10 = 0, a11 = 0, a12 = 0;
#pragma unroll 8
    for (int q = 0; q < 64; q++) {
        float4 wr = wr4[q], wz = wz4[q], wn = wn4[q];
        float4 x = h0[q], y = h1[q];
        a00 += x.x * wr.x + x.y * wr.y + x.z * wr.z + x.w * wr.w;
        a01 += x.x * wz.x + x.y * wz.y + x.z * wz.z + x.w * wz.w;
        a02 += x.x * wn.x + x.y * wn.y + x.z * wn.z + x.w * wn.w;
        a10 += y.x * wr.x + y.y * wr.y + y.z * wr.z + y.w * wr.w;
        a11 += y.x * wz.x + y.y * wz.y + y.z * wz.z + y.w * wz.w;
        a12 += y.x * wn.x + y.y * wn.y + y.z * wn.z + y.w * wn.w;
    }
    int cg = cb0 + c;
    float bhr = bh[cg], bhz = bh[256 + cg], bhn = bh[512 + cg];
#pragma unroll
    for (int rr2 = 0; rr2 < 2; rr2++) {
        int b = rb0 + rp * 2 + rr2;
        const float* x = g_xp + ((size_t)b * TT + t) * 768;
        float hr = (rr2 ? a10 : a00) + bhr;
        float hz = (rr2 ? a11 : a01) + bhz;
        float hn = (rr2 ? a12 : a02) + bhn;
        float rg = 1.f / (1.f + expf(-(x[cg] + hr)));
        float zg = 1.f / (1.f + expf(-(x[256 + cg] + hz)));
        float ng = tanhf(x[512 + cg] + rg * hn);
        float hp = hs[(rp * 2 + rr2) * 256 + cg];
        g_c[((size_t)b * TT + t) * CC + cg] = (1.f - zg) * ng + zg * hp;
    }
}

// ---------------- fused pred GEMM + norm + logits + LSE/argmax per (k,t) ----------------
// grid (500, 12), block 256
#define LOSS_SMEM ((2 * 128 * 132 + 128 + 16) * 4)
__global__ __launch_bounds__(256) void k_loss(const float* __restrict__ Wkw,
                                              const float* __restrict__ Wkb) {
    extern __shared__ float sm[];
    float* Psm = sm;                  // 128x132: raw pred, later logits
    float* Zsm = sm + 128 * 132;      // 128x132: zf tile (aliases As/Bs)
    float* As = Zsm;                  // 32x132  (stage1, [kk][r])
    float* Bs = Zsm + 32 * 132;       // 32x132  (stage1, [kk][d])
    float* rnorm = sm + 2 * 128 * 132;
    float* red = rnorm + 128;

    int t = blockIdx.x, k = blockIdx.y;
    int tid = threadIdx.x;
    int tx = tid & 15, ty = tid >> 4;
    int rows[8], cols[8];
#pragma unroll
    for (int i = 0; i < 8; i++) {
        rows[i] = (i < 4) ? ty * 4 + i : 64 + ty * 4 + i - 4;
        cols[i] = (i < 4) ? tx * 4 + i : 64 + tx * 4 + i - 4;
    }

    // stage 1: P = c_t @ Wk[k]  (128x128, K=256)
    float acc[8][8] = {};
    for (int kc = 0; kc < CC; kc += 32) {
        for (int i = tid; i < 4096; i += 256) {
            int r = i >> 5, kk = i & 31;
            As[kk * 132 + r] = g_c[((size_t)r * TT + t) * CC + kc + kk];
        }
        for (int i = tid; i < 4096; i += 256) {
            int kk = i >> 7, d = i & 127;
            Bs[kk * 132 + d] = Wkw[((size_t)k * CC + kc + kk) * DD + d];
        }
        __syncthreads();
#pragma unroll
        for (int kk = 0; kk < 32; kk++) {
            float4 a1 = *(const float4*)&As[kk * 132 + ty * 4];
            float4 a2 = *(const float4*)&As[kk * 132 + 64 + ty * 4];
            float4 b1 = *(const float4*)&Bs[kk * 132 + tx * 4];
            float4 b2 = *(const float4*)&Bs[kk * 132 + 64 + tx * 4];
            float av[8] = {a1.x, a1.y, a1.z, a1.w, a2.x, a2.y, a2.z, a2.w};
            float bv[8] = {b1.x, b1.y, b1.z, b1.w, b2.x, b2.y, b2.z, b2.w};
#pragma unroll
            for (int i = 0; i < 8; i++)
#pragma unroll
                for (int j = 0; j < 8; j++) acc[i][j] += av[i] * bv[j];
        }
        __syncthreads();
    }
    // bias + stash raw pred
#pragma unroll
    for (int i = 0; i < 8; i++)
#pragma unroll
        for (int j = 0; j < 8; j++)
            Psm[rows[i] * 132 + cols[j]] = acc[i][j] + Wkb[k * DD + cols[j]];
    __syncthreads();

    // per-row 1/||P||  (normalization commutes with the dot product)
    if (tid < 128) {
        const float4* p = (const float4*)&Psm[tid * 132];
        float ss = 0.f;
#pragma unroll
        for (int q = 0; q < 32; q++) {
            float4 v = p[q];
            ss += v.x * v.x + v.y * v.y + v.z * v.z + v.w * v.w;
        }
        rnorm[tid] = 1.f / fmaxf(sqrtf(ss), 1e-12f);
    }
    // load zf tile: Z[c][d] = z[c, t+k+1, d]
    for (int i = tid; i < 16384; i += 256) {
        int cidx = i >> 7, d = i & 127;
        Zsm[cidx * 132 + d] = g_z[((size_t)cidx * TT + t + k + 1) * DD + d];
    }
    __syncthreads();

    // stage 2: S = P @ Z^T  (128x128, K=128)
    float acc2[8][8] = {};
#pragma unroll 2
    for (int d = 0; d < 128; d += 4) {
        float4 pv[8], zv[8];
#pragma unroll
        for (int i = 0; i < 8; i++) pv[i] = *(const float4*)&Psm[rows[i] * 132 + d];
#pragma unroll
        for (int j = 0; j < 8; j++) zv[j] = *(const float4*)&Zsm[cols[j] * 132 + d];
#pragma unroll
        for (int i = 0; i < 8; i++)
#pragma unroll
            for (int j = 0; j < 8; j++)
                acc2[i][j] += pv[i].x * zv[j].x + pv[i].y * zv[j].y +
                              pv[i].z * zv[j].z + pv[i].w * zv[j].w;
    }
    __syncthreads();  // done reading raw P
    // logits = rnorm[b] * S / TEMP  (TEMP = 0.1)
#pragma unroll
    for (int i = 0; i < 8; i++) {
        float rn = rnorm[rows[i]] * 10.0f;
#pragma unroll
        for (int j = 0; j < 8; j++)
            Psm[rows[i] * 132 + cols[j]] = acc2[i][j] * rn;
    }
    __syncthreads();

    // per-row LSE, diag, argmax
    float lossv = 0.f;
    int corr = 0;
    if (tid < 128) {
        const float* L = &Psm[tid * 132];
        float m = -1e30f;
        int am = 0;
        for (int cc = 0; cc < 128; cc++) {
            float v = L[cc];
            if (v > m) { m = v; am = cc; }
        }
        float s = 0.f;
        for (int cc = 0; cc < 128; cc++) s += expf(L[cc] - m);
        lossv = m + logf(s) - L[tid];
        corr = (am == tid) ? 1 : 0;
    }
#pragma unroll
    for (int o = 16; o; o >>= 1) {
        lossv += __shfl_xor_sync(0xffffffffu, lossv, o);
        corr += __shfl_xor_sync(0xffffffffu, corr, o);
    }
    int wid = tid >> 5;
    if ((tid & 31) == 0) {
        red[wid] = lossv;
        ((int*)red)[8 + wid] = corr;
    }
    __syncthreads();
    if (tid == 0) {
        float s = 0.f;
        int ct = 0;
        for (int w = 0; w < 8; w++) { s += red[w]; ct += ((int*)red)[8 + w]; }
        atomicAdd(&g_loss, (double)s);
        atomicAdd(&g_cnt, ct);
    }
}

// ---------------- finalize scalars ----------------
__global__ void k_fin(float* out) {
    const double n = (double)KS * TP * BB;
    out[0] = (float)(g_loss / n);
    out[1] = (float)(100.0 * (double)g_cnt / n);
}

// ---------------- copy z_seq, c_seq into d_out ----------------
__global__ void k_copy(float* out, long long out_size) {
    size_t i0 = (size_t)blockIdx.x * blockDim.x + threadIdx.x;
    size_t stride = (size_t)gridDim.x * blockDim.x;
    const size_t NZ = (size_t)BB * TT * DD;
    const size_t NC = (size_t)BB * TT * CC;
    size_t avail = (out_size > 2) ? (size_t)(out_size - 2) : 0;
    size_t nz = NZ < avail ? NZ : avail;
    size_t nc2 = (avail > NZ) ? ((NC < avail - NZ) ? NC : avail - NZ) : 0;
    float2* oz = (float2*)(out + 2);
    const float2* z2 = (const float2*)g_z;
    for (size_t i = i0; i < nz / 2; i += stride) oz[i] = z2[i];
    float2* oc = (float2*)(out + 2 + NZ);
    const float2* c2 = (const float2*)g_c;
    for (size_t i = i0; i < nc2 / 2; i += stride) oc[i] = c2[i];
}

extern "C" void kernel_launch(void* const* d_in, const int* in_sizes, int n_in,
                              void* d_out, int out_size) {
    const float* rr  = (const float*)d_in[0];
    const float* We  = (const float*)d_in[1];
    const float* be  = (const float*)d_in[2];
    const float* Wi  = (const float*)d_in[3];
    const float* Wh  = (const float*)d_in[4];
    const float* bi  = (const float*)d_in[5];
    const float* bh  = (const float*)d_in[6];
    const float* Wkw = (const float*)d_in[7];
    const float* Wkb = (const float*)d_in[8];
    float* out = (float*)d_out;

    cudaFuncSetAttribute(k_gru, cudaFuncAttributeMaxDynamicSharedMemorySize, GRU_SMEM);
    cudaFuncSetAttribute(k_loss, cudaFuncAttributeMaxDynamicSharedMemorySize, LOSS_SMEM);

    k_init<<<1, 1>>>();
    k_z<<<dim3(TT / 64, BB), 128>>>(rr, We, be);
    k_wht<<<(3 * CC * CC + 255) / 256, 256>>>(Wh);
    k_xproj<<<dim3(6, (BB * TT) / 128), 256>>>(Wi, bi);
    for (int t = 0; t < TT; t++)
        k_gru<<<dim3(CC / 32, BB / 8), 128, GRU_SMEM>>>(bh, t);
    k_loss<<<dim3(TP, KS), 256, LOSS_SMEM>>>(Wkw, Wkb);
    k_fin<<<1, 1>>>(out);
    k_copy<<<2048, 256>>>(out, (long long)out_size);
}